// round 17
// baseline (speedup 1.0000x reference)
#include <cuda_runtime.h>
#include <cuda_fp16.h>

#define Nn 100000
#define Ee 1600000
#define Dd 128
#define Hh 256
#define Ll 40
#define NB 98   // ceil(Nn / 1024)

// ---------------- scratch ------------------------------------------------------
__device__ int   g_degi[Nn];
__device__ int   g_offs[Nn + 1];
__device__ int   g_col[Ee];
__device__ int   g_part[NB];
__device__ float g_dinv[Nn];
__device__ __half g_featA[(size_t)Nn * Dd];   // feature ping
__device__ __half g_featB[(size_t)Nn * Dd];   // feature pong
__device__ __half g_hidH[(size_t)Nn * Hh];    // fp16 MLP hidden
// transposed fp16 hi/lo weights [N][K], packed:
//   W0,W1,W2: 128x128 ; Wm1: 256x128 ; Wm2: 64(pad from 40)x256
#define WT0 0
#define WT1 16384
#define WT2 32768
#define WTM1 49152
#define WTM2 81920
#define WTOT 98304
__device__ __half g_wtH[WTOT];
__device__ __half g_wtL[WTOT];

// ---------------- CSR build ----------------------------------------------------
__global__ void k_zero(int* __restrict__ a, int n) {
    int i = blockIdx.x * blockDim.x + threadIdx.x;
    if (i < n) a[i] = 0;
}

__global__ void k_count(const int* __restrict__ ei, int* __restrict__ degi, int e) {
    int i = blockIdx.x * blockDim.x + threadIdx.x;
    if (i < e) atomicAdd(&degi[ei[i]], 1);
}

// block partial sums + dinv (fused)
__global__ void k_scanA(const int* __restrict__ degi, int* __restrict__ part,
                        float* __restrict__ dinv) {
    __shared__ int s[1024];
    int i = blockIdx.x * 1024 + threadIdx.x;
    int v = (i < Nn) ? degi[i] : 0;
    if (i < Nn) dinv[i] = rsqrtf((float)v + 1.0f);
    s[threadIdx.x] = v;
    __syncthreads();
    for (int d = 512; d > 0; d >>= 1) {
        if (threadIdx.x < d) s[threadIdx.x] += s[threadIdx.x + d];
        __syncthreads();
    }
    if (threadIdx.x == 0) part[blockIdx.x] = s[0];
}

// per-block exclusive scan; base computed in-block from partials (fused scanB)
__global__ void k_scanC(const int* __restrict__ degi, const int* __restrict__ part,
                        int* __restrict__ offs) {
    __shared__ int sp[128];
    __shared__ int s[1024];
    int t = threadIdx.x;
    if (t < 128) sp[t] = (t < NB) ? part[t] : 0;
    __syncthreads();
    for (int d = 1; d < 128; d <<= 1) {
        int u = 0;
        if (t < 128 && t >= d) u = sp[t - d];
        __syncthreads();
        if (t < 128) sp[t] += u;
        __syncthreads();
    }
    int base = (blockIdx.x == 0) ? 0 : sp[blockIdx.x - 1];
    int i = blockIdx.x * 1024 + t;
    int v = (i < Nn) ? degi[i] : 0;
    s[t] = v;
    __syncthreads();
    for (int d = 1; d < 1024; d <<= 1) {
        int u = (t >= d) ? s[t - d] : 0;
        __syncthreads();
        s[t] += u;
        __syncthreads();
    }
    int exc = s[t] - v + base;
    if (i < Nn) {
        offs[i] = exc;
        if (i == Nn - 1) offs[Nn] = exc + v;
    }
}

__global__ void k_fill(const int* __restrict__ ei, const int* __restrict__ offs,
                       int* __restrict__ degi, int* __restrict__ col, int e) {
    int i = blockIdx.x * blockDim.x + threadIdx.x;
    if (i < e) {
        int r = ei[i];
        int c = ei[e + i];
        int pos = offs[r] + atomicSub(&degi[r], 1) - 1;
        col[pos] = c;
    }
}

// ---------------- fused weight conversion: all 5 weights -> fp16 hi/lo --------
__global__ void k_wconv_all(const float* __restrict__ W0, const float* __restrict__ W1,
                            const float* __restrict__ W2, const float* __restrict__ Wm1,
                            const float* __restrict__ Wm2,
                            __half* __restrict__ H, __half* __restrict__ L) {
    int i = blockIdx.x * blockDim.x + threadIdx.x;
    if (i >= WTOT) return;
    float w;
    if (i < WTM1) {                       // W0/W1/W2: dest [n][k], K=128, N=128
        const float* W = (i < WT1) ? W0 : (i < WT2) ? W1 : W2;
        int j = i & 16383;
        int n = j >> 7, k = j & 127;
        w = W[k * 128 + n];
    } else if (i < WTM2) {                // Wm1: dest [n][k], n<256, K=128
        int j = i - WTM1;
        int n = j >> 7, k = j & 127;
        w = Wm1[k * 256 + n];
    } else {                              // Wm2: dest [n][k], n<64 (pad 40), K=256
        int j = i - WTM2;
        int n = j >> 8, k = j & 255;
        w = (n < Ll) ? Wm2[k * Ll + n] : 0.f;
    }
    __half h = __float2half_rn(w);
    __half l = __float2half_rn(w - __half2float(h));
    H[i] = h;
    L[i] = l;
}

// ---------------- fp32 -> prescaled fp16: xh = fp16(dinv[row] * x) ------------
__global__ void k_f2h(const float4* __restrict__ x, const float* __restrict__ dinv,
                      uint2* __restrict__ xh, int n4) {
    int t = blockIdx.x * blockDim.x + threadIdx.x;
    if (t < n4) {
        float d = __ldg(&dinv[t >> 5]);
        float4 v = x[t];
        __half2 a = __floats2half2_rn(v.x * d, v.y * d);
        __half2 b = __floats2half2_rn(v.z * d, v.w * d);
        uint2 u;
        u.x = *(unsigned*)&a;
        u.y = *(unsigned*)&b;
        xh[t] = u;
    }
}

// ---------------- MMA helpers --------------------------------------------------
__device__ __forceinline__ void mma16816h(float* c, const unsigned* a, unsigned b0, unsigned b1) {
    asm volatile(
        "mma.sync.aligned.m16n8k16.row.col.f32.f16.f16.f32 "
        "{%0,%1,%2,%3},{%4,%5,%6,%7},{%8,%9},{%0,%1,%2,%3};"
        : "+f"(c[0]), "+f"(c[1]), "+f"(c[2]), "+f"(c[3])
        : "r"(a[0]), "r"(a[1]), "r"(a[2]), "r"(a[3]), "r"(b0), "r"(b1));
}

__device__ __forceinline__ void ldsm4(unsigned addr, unsigned& r0, unsigned& r1,
                                      unsigned& r2, unsigned& r3) {
    asm volatile("ldmatrix.sync.aligned.m8n8.x4.shared.b16 {%0,%1,%2,%3}, [%4];"
                 : "=r"(r0), "=r"(r1), "=r"(r2), "=r"(r3) : "r"(addr));
}

// ---------------- FUSED layer: gather (into smem) + GEMM + epilogue -----------
// 512 threads, persistent over M tiles. W (128x128 hi/lo) staged once.
// src features prescaled fp16; out = fp16( [dinv*] relu(agg @ W^T + b) ).
#define LKSTR 136
template<bool PRESCALE_OUT>
__global__ void __launch_bounds__(512, 2) k_layer(
    const int* __restrict__ offs, const int* __restrict__ col,
    const float* __restrict__ dinv, const uint4* __restrict__ src,
    const __half* __restrict__ WtH, const __half* __restrict__ WtL,
    const float* __restrict__ bias, __half* __restrict__ outh) {
    extern __shared__ __half smb[];
    __half* As  = smb;                     // 128 x LKSTR
    __half* WsH = As + 128 * LKSTR;
    __half* WsL = WsH + 128 * LKSTR;

    int tid = threadIdx.x;

    // stage W once: 128 rows x 16 uint4
    {
        const uint4* GH = (const uint4*)WtH;
        const uint4* GL = (const uint4*)WtL;
#pragma unroll
        for (int it = 0; it < 4; it++) {
            int i = tid + 512 * it;        // 0..2047
            int r = i >> 4, c = i & 15;
            *(uint4*)&WsH[r * LKSTR + c * 8] = GH[i];
            *(uint4*)&WsL[r * LKSTR + c * 8] = GL[i];
        }
    }

    int lane = tid & 31, wid = tid >> 5;   // 16 warps
    int l16 = lane & 15, half = lane >> 4;
    int wm = (wid & 3) * 32;
    int wn = (wid >> 2) * 32;
    int g = lane >> 2, t = lane & 3;

    unsigned aOff = (unsigned)__cvta_generic_to_shared(As) +
                    (((wm + (lane & 15)) * LKSTR + (lane >> 4) * 8) << 1);
    unsigned bOffH = (unsigned)__cvta_generic_to_shared(WsH) +
                     (((wn + (lane & 7) + ((lane >> 4) & 1) * 8) * LKSTR +
                       ((lane >> 3) & 1) * 8) << 1);
    unsigned bOffL = bOffH + 128 * LKSTR * 2;

    int tiles = (Nn + 127) >> 7;
    for (int mb = blockIdx.x; mb < tiles; mb += gridDim.x) {
        int m0 = mb << 7;

        // ---- gather phase: warp handles rows [wid*8, wid*8+8), 2 per pass ----
#pragma unroll 1
        for (int s = 0; s < 4; s++) {
            int r = wid * 8 + 2 * s + half;
            int node = m0 + r;
            if (node < Nn) {
                uint4 u = __ldg(&src[(size_t)node * 16 + l16]);   // self
                float2 f0 = __half22float2(*(__half2*)&u.x);
                float2 f1 = __half22float2(*(__half2*)&u.y);
                float2 f2 = __half22float2(*(__half2*)&u.z);
                float2 f3 = __half22float2(*(__half2*)&u.w);
                float a0 = f0.x, a1 = f0.y, a2 = f1.x, a3 = f1.y;
                float a4 = f2.x, a5 = f2.y, a6 = f3.x, a7 = f3.y;

                int beg = __ldg(&offs[node]), end = __ldg(&offs[node + 1]);
                int c = (beg < end) ? __ldg(&col[beg]) : 0;
                for (int j = beg; j < end; j++) {
                    int cn = (j + 1 < end) ? __ldg(&col[j + 1]) : 0;
                    uint4 v = __ldg(&src[(size_t)c * 16 + l16]);
                    float2 g0 = __half22float2(*(__half2*)&v.x);
                    float2 g1 = __half22float2(*(__half2*)&v.y);
                    float2 g2 = __half22float2(*(__half2*)&v.z);
                    float2 g3 = __half22float2(*(__half2*)&v.w);
                    a0 += g0.x; a1 += g0.y; a2 += g1.x; a3 += g1.y;
                    a4 += g2.x; a5 += g2.y; a6 += g3.x; a7 += g3.y;
                    c = cn;
                }
                float di = __ldg(&dinv[node]);
                __half2 p0 = __floats2half2_rn(a0 * di, a1 * di);
                __half2 p1 = __floats2half2_rn(a2 * di, a3 * di);
                __half2 p2 = __floats2half2_rn(a4 * di, a5 * di);
                __half2 p3 = __floats2half2_rn(a6 * di, a7 * di);
                uint4 o;
                o.x = *(unsigned*)&p0;
                o.y = *(unsigned*)&p1;
                o.z = *(unsigned*)&p2;
                o.w = *(unsigned*)&p3;
                *(uint4*)&As[r * LKSTR + l16 * 8] = o;
            }
        }
        __syncthreads();

        // ---- MMA phase (R16-validated ldmatrix layout; NFRAG=4, NPAIR=2) ----
        float acc[2][4][4];
#pragma unroll
        for (int mt = 0; mt < 2; mt++)
#pragma unroll
            for (int nt = 0; nt < 4; nt++)
#pragma unroll
                for (int q = 0; q < 4; q++) acc[mt][nt][q] = 0.f;

#pragma unroll
        for (int ks = 0; ks < 8; ks++) {
            unsigned ko = (unsigned)(ks * 32);
            unsigned aF[2][4];
            ldsm4(aOff + ko, aF[0][0], aF[0][1], aF[0][2], aF[0][3]);
            ldsm4(aOff + 16 * LKSTR * 2 + ko, aF[1][0], aF[1][1], aF[1][2], aF[1][3]);
#pragma unroll
            for (int p = 0; p < 2; p++) {
                unsigned bH[4], bL[4];
                ldsm4(bOffH + p * 16 * LKSTR * 2 + ko, bH[0], bH[1], bH[2], bH[3]);
                ldsm4(bOffL + p * 16 * LKSTR * 2 + ko, bL[0], bL[1], bL[2], bL[3]);
#pragma unroll
                for (int mt = 0; mt < 2; mt++) {
                    mma16816h(acc[mt][2 * p],     aF[mt], bH[0], bH[1]);
                    mma16816h(acc[mt][2 * p],     aF[mt], bL[0], bL[1]);
                    mma16816h(acc[mt][2 * p + 1], aF[mt], bH[2], bH[3]);
                    mma16816h(acc[mt][2 * p + 1], aF[mt], bL[2], bL[3]);
                }
            }
        }

        // ---- epilogue: fp16 store (optionally prescaled by dinv) ----
#pragma unroll
        for (int nt = 0; nt < 4; nt++) {
            int cg = wn + nt * 8 + 2 * t;
            float bv0 = __ldg(&bias[cg]);
            float bv1 = __ldg(&bias[cg + 1]);
#pragma unroll
            for (int mt = 0; mt < 2; mt++) {
                int r0 = m0 + wm + mt * 16 + g;
                float v0 = fmaxf(acc[mt][nt][0] + bv0, 0.f);
                float v1 = fmaxf(acc[mt][nt][1] + bv1, 0.f);
                float v2 = fmaxf(acc[mt][nt][2] + bv0, 0.f);
                float v3 = fmaxf(acc[mt][nt][3] + bv1, 0.f);
                float d0 = 1.f, d1 = 1.f;
                if (PRESCALE_OUT) {
                    d0 = (r0 < Nn) ? __ldg(&dinv[r0]) : 0.f;
                    d1 = (r0 + 8 < Nn) ? __ldg(&dinv[r0 + 8]) : 0.f;
                }
                if (r0 < Nn)
                    *(__half2*)&outh[(size_t)r0 * 128 + cg] = __floats2half2_rn(v0 * d0, v1 * d0);
                if (r0 + 8 < Nn)
                    *(__half2*)&outh[(size_t)(r0 + 8) * 128 + cg] = __floats2half2_rn(v2 * d1, v3 * d1);
            }
        }
        __syncthreads();   // protect As before next tile's gather writes
    }
}

// ---------------- standalone fp16 2-MMA GEMM (MLP, R16 proven) ----------------
template<int KEL, int NTILE, int NVALID, bool RELU, bool OUTH>
__global__ void k_gemm_tc(const __half* __restrict__ Ah, const __half* __restrict__ WtH,
                          const __half* __restrict__ WtL, const float* __restrict__ bias,
                          void* __restrict__ outv, int nrows, int ldc) {
    constexpr int KSTR  = KEL + 8;
    constexpr int NT    = NTILE / 2;
    constexpr int NFRAG = NT / 8;
    constexpr int NPAIR = NFRAG / 2;
    extern __shared__ __half smb[];
    __half* As  = smb;
    __half* WsH = As + 128 * KSTR;
    __half* WsL = WsH + NTILE * KSTR;

    int tid = threadIdx.x;
    int n0 = blockIdx.y * NTILE;

    constexpr int C8 = KEL / 8;
    {
        const uint4* GH = (const uint4*)(WtH + (size_t)n0 * KEL);
        const uint4* GL = (const uint4*)(WtL + (size_t)n0 * KEL);
#pragma unroll
        for (int it = 0; it < NTILE * C8 / 256; it++) {
            int i = tid + 256 * it;
            int r = i / C8, c = i % C8;
            *(uint4*)((char*)WsH + r * (KSTR * 2) + c * 16) = GH[r * C8 + c];
            *(uint4*)((char*)WsL + r * (KSTR * 2) + c * 16) = GL[r * C8 + c];
        }
    }

    int lane = tid & 31, wid = tid >> 5;
    int wm = (wid & 3) * 32;
    int wn = (wid >> 2) * NT;
    int g = lane >> 2, t = lane & 3;

    unsigned aOff = (unsigned)__cvta_generic_to_shared(As) +
                    (((wm + (lane & 15)) * KSTR + (lane >> 4) * 8) << 1);
    unsigned bOffH = (unsigned)__cvta_generic_to_shared(WsH) +
                     (((wn + (lane & 7) + ((lane >> 4) & 1) * 8) * KSTR +
                       ((lane >> 3) & 1) * 8) << 1);
    unsigned bOffL = bOffH + NTILE * KSTR * 2;

    float bv[NFRAG][2];
    bool  cokv[NFRAG];
#pragma unroll
    for (int nt = 0; nt < NFRAG; nt++) {
        int cg = n0 + wn + nt * 8 + 2 * t;
        cokv[nt] = cg < NVALID;
        bv[nt][0] = cokv[nt] ? bias[cg] : 0.f;
        bv[nt][1] = cokv[nt] ? bias[cg + 1] : 0.f;
    }

    int tiles = (nrows + 127) >> 7;
    for (int mb = blockIdx.x; mb < tiles; mb += gridDim.x) {
        int m0 = mb << 7;
        {
            const uint4* GA = (const uint4*)Ah;
#pragma unroll
            for (int it = 0; it < 128 * C8 / 256; it++) {
                int i = tid + 256 * it;
                int r = i / C8, c = i % C8;
                uint4 v = (m0 + r < nrows) ? __ldg(&GA[(size_t)(m0 + r) * C8 + c])
                                           : make_uint4(0u, 0u, 0u, 0u);
                *(uint4*)&As[r * KSTR + c * 8] = v;
            }
        }
        __syncthreads();

        float acc[2][NFRAG][4];
#pragma unroll
        for (int mt = 0; mt < 2; mt++)
#pragma unroll
            for (int nt = 0; nt < NFRAG; nt++)
#pragma unroll
                for (int q = 0; q < 4; q++) acc[mt][nt][q] = 0.f;

#pragma unroll
        for (int ks = 0; ks < KEL / 16; ks++) {
            unsigned ko = (unsigned)(ks * 32);
            unsigned aF[2][4];
            ldsm4(aOff + ko, aF[0][0], aF[0][1], aF[0][2], aF[0][3]);
            ldsm4(aOff + 16 * KSTR * 2 + ko, aF[1][0], aF[1][1], aF[1][2], aF[1][3]);
#pragma unroll
            for (int p = 0; p < NPAIR; p++) {
                unsigned bH[4], bL[4];
                ldsm4(bOffH + p * 16 * KSTR * 2 + ko, bH[0], bH[1], bH[2], bH[3]);
                ldsm4(bOffL + p * 16 * KSTR * 2 + ko, bL[0], bL[1], bL[2], bL[3]);
#pragma unroll
                for (int mt = 0; mt < 2; mt++) {
                    mma16816h(acc[mt][2 * p],     aF[mt], bH[0], bH[1]);
                    mma16816h(acc[mt][2 * p],     aF[mt], bL[0], bL[1]);
                    mma16816h(acc[mt][2 * p + 1], aF[mt], bH[2], bH[3]);
                    mma16816h(acc[mt][2 * p + 1], aF[mt], bL[2], bL[3]);
                }
            }
        }

#pragma unroll
        for (int nt = 0; nt < NFRAG; nt++) {
            int cg = n0 + wn + nt * 8 + 2 * t;
            bool cok = cokv[nt];
            float bv0 = bv[nt][0], bv1 = bv[nt][1];
#pragma unroll
            for (int mt = 0; mt < 2; mt++) {
                int r0 = m0 + wm + mt * 16 + g;
                float v0 = acc[mt][nt][0] + bv0, v1 = acc[mt][nt][1] + bv1;
                float v2 = acc[mt][nt][2] + bv0, v3 = acc[mt][nt][3] + bv1;
                if (RELU) {
                    v0 = fmaxf(v0, 0.f); v1 = fmaxf(v1, 0.f);
                    v2 = fmaxf(v2, 0.f); v3 = fmaxf(v3, 0.f);
                }
                if (OUTH) {
                    __half* oh = (__half*)outv;
                    if (cok && r0 < nrows)
                        *(__half2*)&oh[(size_t)r0 * ldc + cg] = __floats2half2_rn(v0, v1);
                    if (cok && r0 + 8 < nrows)
                        *(__half2*)&oh[(size_t)(r0 + 8) * ldc + cg] = __floats2half2_rn(v2, v3);
                } else {
                    float* of = (float*)outv;
                    if (cok && r0 < nrows) {
                        of[(size_t)r0 * ldc + cg]     = v0;
                        of[(size_t)r0 * ldc + cg + 1] = v1;
                    }
                    if (cok && r0 + 8 < nrows) {
                        of[(size_t)(r0 + 8) * ldc + cg]     = v2;
                        of[(size_t)(r0 + 8) * ldc + cg + 1] = v3;
                    }
                }
            }
        }
        __syncthreads();
    }
}

#define SMEM_TC  (3 * 128 * 136 * 2)               // 104448 (layer + MLP1)
#define SMEM_M2  ((128 + 2 * 64) * 264 * 2)        // 135168 (MLP2)

extern "C" void kernel_launch(void* const* d_in, const int* in_sizes, int n_in,
                              void* d_out, int out_size) {
    const float* x   = (const float*)d_in[0];
    const int*   ei  = (const int*)  d_in[1];
    const float* W0  = (const float*)d_in[2];
    const float* b0  = (const float*)d_in[3];
    const float* W1  = (const float*)d_in[4];
    const float* b1  = (const float*)d_in[5];
    const float* W2  = (const float*)d_in[6];
    const float* b2  = (const float*)d_in[7];
    const float* Wm1 = (const float*)d_in[8];
    const float* bm1 = (const float*)d_in[9];
    const float* Wm2 = (const float*)d_in[10];
    const float* bm2 = (const float*)d_in[11];
    float* out = (float*)d_out;

    const int n = Nn, e = Ee;

    int *degi, *offs, *col, *part;
    float *dinv;
    __half *fA, *fB, *hidH, *wtH, *wtL;
    cudaGetSymbolAddress((void**)&degi, g_degi);
    cudaGetSymbolAddress((void**)&offs, g_offs);
    cudaGetSymbolAddress((void**)&col,  g_col);
    cudaGetSymbolAddress((void**)&part, g_part);
    cudaGetSymbolAddress((void**)&dinv, g_dinv);
    cudaGetSymbolAddress((void**)&fA,   g_featA);
    cudaGetSymbolAddress((void**)&fB,   g_featB);
    cudaGetSymbolAddress((void**)&hidH, g_hidH);
    cudaGetSymbolAddress((void**)&wtH,  g_wtH);
    cudaGetSymbolAddress((void**)&wtL,  g_wtL);

    cudaFuncSetAttribute(k_layer<true>,
                         cudaFuncAttributeMaxDynamicSharedMemorySize, SMEM_TC);
    cudaFuncSetAttribute(k_layer<false>,
                         cudaFuncAttributeMaxDynamicSharedMemorySize, SMEM_TC);
    cudaFuncSetAttribute(k_gemm_tc<128, 128, 256, true, true>,
                         cudaFuncAttributeMaxDynamicSharedMemorySize, SMEM_TC);
    cudaFuncSetAttribute(k_gemm_tc<256, 64, 40, false, false>,
                         cudaFuncAttributeMaxDynamicSharedMemorySize, SMEM_M2);

    const int TB = 256;
    dim3 gN((n + TB - 1) / TB);
    dim3 gE((e + TB - 1) / TB);
    dim3 gF2H(((size_t)n * 32 + TB - 1) / TB);
    dim3 gL(296);        // fused layer: 2 CTAs/SM persistent
    dim3 gP2(148, 2);    // MLP1
    dim3 gP1(148, 1);    // MLP2

    // ---- CSR build + normalization ----
    k_zero <<<gN, TB>>>(degi, n);
    k_count<<<gE, TB>>>(ei, degi, e);
    k_scanA<<<NB, 1024>>>(degi, part, dinv);
    k_scanC<<<NB, 1024>>>(degi, part, offs);
    k_fill <<<gE, TB>>>(ei, offs, degi, col, e);

    // ---- fused weight conversion ----
    k_wconv_all<<<(WTOT + 255) / 256, 256>>>(W0, W1, W2, Wm1, Wm2, wtH, wtL);

    // ---- x -> prescaled fp16 (featA) ----
    k_f2h<<<gF2H, TB>>>((const float4*)x, dinv, (uint2*)fA, n * 32);

    // ---- fused layers (ping-pong featA <-> featB) ----
    k_layer<true ><<<gL, 512, SMEM_TC>>>(offs, col, dinv, (const uint4*)fA,
                                         wtH + WT0, wtL + WT0, b0, fB);
    k_layer<true ><<<gL, 512, SMEM_TC>>>(offs, col, dinv, (const uint4*)fB,
                                         wtH + WT1, wtL + WT1, b1, fA);
    k_layer<false><<<gL, 512, SMEM_TC>>>(offs, col, dinv, (const uint4*)fA,
                                         wtH + WT2, wtL + WT2, b2, fB);

    // ---- MLP: h3(fp16, featB) -> hid(fp16) -> out(fp32) ----
    k_gemm_tc<128, 128, 256, true, true><<<gP2, TB, SMEM_TC>>>(
        fB, wtH + WTM1, wtL + WTM1, bm1, hidH, n, 256);
    k_gemm_tc<256, 64, 40, false, false><<<gP1, TB, SMEM_M2>>>(
        hidH, wtH + WTM2, wtL + WTM2, bm2, out, n, 40);
}